// round 14
// baseline (speedup 1.0000x reference)
#include <cuda_runtime.h>
#include <cuda_bf16.h>
#include <mma.h>
#include <cstdint>

using namespace nvcuda;

#define BATCH 4
#define T_SEQ 1024
#define CDIM  512
#define NH    8
#define HDIM  64
#define SCALE_F 0.125f

// ---------------------------------------------------------------------------
// Scratch (no cudaMalloc allowed). Referenced ONLY from device code.
// ---------------------------------------------------------------------------
__device__ __align__(16) float g_q[BATCH * NH * T_SEQ * HDIM];
__device__ __align__(16) float g_k[BATCH * NH * T_SEQ * HDIM];
__device__ __align__(16) float g_v[BATCH * NH * T_SEQ * HDIM];

__device__ __align__(16) __nv_bfloat16 g_xhi[BATCH * T_SEQ * CDIM];
__device__ __align__(16) __nv_bfloat16 g_xlo[BATCH * T_SEQ * CDIM];
__device__ __align__(16) __nv_bfloat16 g_whi[4 * CDIM * CDIM];
__device__ __align__(16) __nv_bfloat16 g_wlo[4 * CDIM * CDIM];
__device__ __align__(16) __nv_bfloat16 g_yhi[BATCH * T_SEQ * CDIM];
__device__ __align__(16) __nv_bfloat16 g_ylo[BATCH * T_SEQ * CDIM];

// K/V in MMA-ready bf16 hi/lo form; V pre-transposed [bh][d][t]
__device__ __align__(16) __nv_bfloat16 g_khi[BATCH * NH * T_SEQ * HDIM];
__device__ __align__(16) __nv_bfloat16 g_klo[BATCH * NH * T_SEQ * HDIM];
__device__ __align__(16) __nv_bfloat16 g_vhi[BATCH * NH * HDIM * T_SEQ];
__device__ __align__(16) __nv_bfloat16 g_vlo[BATCH * NH * HDIM * T_SEQ];

// ---------------------------------------------------------------------------
// helpers
// ---------------------------------------------------------------------------
__device__ __forceinline__ void split4(const float* f, __nv_bfloat16* h,
                                       __nv_bfloat16* l) {
#pragma unroll
    for (int j = 0; j < 4; j++) {
        h[j] = __float2bfloat16(f[j]);
        l[j] = __float2bfloat16(f[j] - __bfloat162float(h[j]));
    }
}

__device__ __forceinline__ void mma_bf16(float* d, const uint32_t* a,
                                         uint32_t b0, uint32_t b1) {
    asm volatile(
        "mma.sync.aligned.m16n8k16.row.col.f32.bf16.bf16.f32 "
        "{%0,%1,%2,%3}, {%4,%5,%6,%7}, {%8,%9}, {%0,%1,%2,%3};"
        : "+f"(d[0]), "+f"(d[1]), "+f"(d[2]), "+f"(d[3])
        : "r"(a[0]), "r"(a[1]), "r"(a[2]), "r"(a[3]), "r"(b0), "r"(b1));
}

__device__ __forceinline__ uint32_t pack_bf2(float lo, float hi) {
    __nv_bfloat162 t = __floats2bfloat162_rn(lo, hi);  // .x = low 16 bits
    return *(uint32_t*)&t;
}

// ---------------------------------------------------------------------------
// fp32 -> bf16 hi/lo split conversions
// ---------------------------------------------------------------------------
__global__ __launch_bounds__(256)
void convert_x(const float* __restrict__ src)
{
    int i = (blockIdx.x * 256 + threadIdx.x) * 4;
    float4 v = *(const float4*)(src + i);
    float f[4] = {v.x, v.y, v.z, v.w};
    __nv_bfloat16 h[4], l[4];
    split4(f, h, l);
    *(uint2*)(g_xhi + i) = *(uint2*)h;
    *(uint2*)(g_xlo + i) = *(uint2*)l;
}

__global__ __launch_bounds__(256)
void convert_w4(const float* __restrict__ w0, const float* __restrict__ w1,
                const float* __restrict__ w2, const float* __restrict__ w3)
{
    int z = blockIdx.y;
    const float* src = (z == 0) ? w0 : (z == 1) ? w1 : (z == 2) ? w2 : w3;
    int i = (blockIdx.x * 256 + threadIdx.x) * 4;
    float4 v = *(const float4*)(src + i);
    float f[4] = {v.x, v.y, v.z, v.w};
    __nv_bfloat16 h[4], l[4];
    split4(f, h, l);
    size_t o = (size_t)z * CDIM * CDIM + i;
    *(uint2*)(g_whi + o) = *(uint2*)h;
    *(uint2*)(g_wlo + o) = *(uint2*)l;
}

// K -> khi/klo [bh][t][d];  V -> vhi/vlo transposed [bh][d][t]
__global__ __launch_bounds__(256)
void convert_kv()
{
    __shared__ float vt[64][68];

    const int bh = blockIdx.y;
    const int t0 = blockIdx.x * 64;
    const int tid = threadIdx.x;
    const size_t base = (size_t)bh * T_SEQ * HDIM;

    for (int i = tid; i < 64 * 16; i += 256) {
        int row = i >> 4, c4 = (i & 15) * 4;
        size_t idx = base + (size_t)(t0 + row) * HDIM + c4;
        float4 v = *(const float4*)&g_k[idx];
        float f[4] = {v.x, v.y, v.z, v.w};
        __nv_bfloat16 h[4], l[4];
        split4(f, h, l);
        *(uint2*)(g_khi + idx) = *(uint2*)h;
        *(uint2*)(g_klo + idx) = *(uint2*)l;
        float4 vv = *(const float4*)&g_v[idx];
        vt[row][c4 + 0] = vv.x; vt[row][c4 + 1] = vv.y;
        vt[row][c4 + 2] = vv.z; vt[row][c4 + 3] = vv.w;
    }
    __syncthreads();

    for (int i = tid; i < 64 * 16; i += 256) {
        int d = i >> 4, tq = (i & 15) * 4;
        float f[4] = {vt[tq][d], vt[tq + 1][d], vt[tq + 2][d], vt[tq + 3][d]};
        __nv_bfloat16 h[4], l[4];
        split4(f, h, l);
        size_t idx = (size_t)bh * HDIM * T_SEQ + (size_t)d * T_SEQ + t0 + tq;
        *(uint2*)(g_vhi + idx) = *(uint2*)h;
        *(uint2*)(g_vlo + idx) = *(uint2*)l;
    }
}

// ---------------------------------------------------------------------------
// Projection GEMMs via wmma, 128x128 tile, BK=32 (passing R13 version)
// ---------------------------------------------------------------------------
#define GP 40
#define MATH 5120

template <int MODE>
__global__ __launch_bounds__(256, 1)
void hm_gemm(const float* __restrict__ bias0, const float* __restrict__ bias1,
             const float* __restrict__ bias2, float* __restrict__ out_proj)
{
    __shared__ __align__(32) __nv_bfloat16 sm[4 * MATH];

    const int tid = threadIdx.x;
    const int wid = tid >> 5;
    const int wm = wid >> 2, wn = wid & 3;

    const int n0 = blockIdx.x * 128;
    const int m0 = blockIdx.y * 128;
    const int z  = (MODE == 0) ? (int)blockIdx.z : 3;

    const float* bias = (MODE == 0) ? ((z == 0) ? bias0 : (z == 1) ? bias1 : bias2)
                                    : bias0;
    float* outp = (MODE == 0) ? ((z == 0) ? g_q : (z == 1) ? g_k : g_v) : out_proj;

    const __nv_bfloat16* Ahi = ((MODE == 0) ? g_xhi : g_yhi) + (size_t)m0 * CDIM;
    const __nv_bfloat16* Alo = ((MODE == 0) ? g_xlo : g_ylo) + (size_t)m0 * CDIM;
    const __nv_bfloat16* Bhi = g_whi + (size_t)z * CDIM * CDIM + (size_t)n0 * CDIM;
    const __nv_bfloat16* Blo = g_wlo + (size_t)z * CDIM * CDIM + (size_t)n0 * CDIM;
    const __nv_bfloat16* srcs[4] = {Ahi, Alo, Bhi, Blo};

    float* sbias = (float*)sm;
    for (int idx = tid; idx < 16 * 128; idx += 256) {
        int r = idx >> 7, c = idx & 127;
        sbias[r * 132 + c] = bias[n0 + c];
    }

    const int lr0 = tid >> 1;
    const int lq0 = (tid & 1) * 2;

    wmma::fragment<wmma::accumulator, 16, 16, 16, float> acc[4][2];
    uint4 pf[4][2];

#pragma unroll
    for (int mat = 0; mat < 4; mat++)
#pragma unroll
        for (int e = 0; e < 2; e++)
            pf[mat][e] = *(const uint4*)(srcs[mat] + (size_t)lr0 * CDIM + (lq0 + e) * 8);

    __syncthreads();
#pragma unroll
    for (int mi = 0; mi < 4; mi++)
#pragma unroll
        for (int ni = 0; ni < 2; ni++)
            wmma::load_matrix_sync(acc[mi][ni], &sbias[wn * 32 + ni * 16], 132,
                                   wmma::mem_row_major);
    __syncthreads();

    for (int kt = 0; kt < CDIM / 32; kt++) {
#pragma unroll
        for (int mat = 0; mat < 4; mat++)
#pragma unroll
            for (int e = 0; e < 2; e++)
                *(uint4*)(sm + mat * MATH + lr0 * GP + (lq0 + e) * 8) = pf[mat][e];
        __syncthreads();

        if (kt < CDIM / 32 - 1) {
            int k0 = (kt + 1) * 32;
#pragma unroll
            for (int mat = 0; mat < 4; mat++)
#pragma unroll
                for (int e = 0; e < 2; e++)
                    pf[mat][e] = *(const uint4*)(srcs[mat] + (size_t)lr0 * CDIM + k0 + (lq0 + e) * 8);
        }

#pragma unroll
        for (int ks = 0; ks < 2; ks++) {
            wmma::fragment<wmma::matrix_a, 16, 16, 16, __nv_bfloat16, wmma::row_major> fah[4], fal[4];
            wmma::fragment<wmma::matrix_b, 16, 16, 16, __nv_bfloat16, wmma::col_major> fbh[2], fbl[2];
#pragma unroll
            for (int mi = 0; mi < 4; mi++) {
                int mr = wm * 64 + mi * 16;
                wmma::load_matrix_sync(fah[mi], &sm[0 * MATH + mr * GP + ks * 16], GP);
                wmma::load_matrix_sync(fal[mi], &sm[1 * MATH + mr * GP + ks * 16], GP);
            }
#pragma unroll
            for (int ni = 0; ni < 2; ni++) {
                int nr = wn * 32 + ni * 16;
                wmma::load_matrix_sync(fbh[ni], &sm[2 * MATH + nr * GP + ks * 16], GP);
                wmma::load_matrix_sync(fbl[ni], &sm[3 * MATH + nr * GP + ks * 16], GP);
            }
#pragma unroll
            for (int mi = 0; mi < 4; mi++)
#pragma unroll
                for (int ni = 0; ni < 2; ni++) {
                    wmma::mma_sync(acc[mi][ni], fah[mi], fbh[ni], acc[mi][ni]);
                    wmma::mma_sync(acc[mi][ni], fah[mi], fbl[ni], acc[mi][ni]);
                    wmma::mma_sync(acc[mi][ni], fal[mi], fbh[ni], acc[mi][ni]);
                }
        }
        __syncthreads();
    }

#pragma unroll
    for (int mi = 0; mi < 4; mi++)
#pragma unroll
        for (int ni = 0; ni < 2; ni++) {
            int m = m0 + wm * 64 + mi * 16;
            int n = n0 + wn * 32 + ni * 16;
            if (MODE == 0) {
                int b_ = m >> 10;
                int t0 = m & 1023;
                int h  = n >> 6;
                int d0 = n & 63;
                float* dst = &outp[(((size_t)(b_ * NH + h)) * T_SEQ + t0) * HDIM + d0];
                wmma::store_matrix_sync(dst, acc[mi][ni], HDIM, wmma::mem_row_major);
            } else {
                wmma::store_matrix_sync(&outp[(size_t)m * CDIM + n], acc[mi][ni],
                                        CDIM, wmma::mem_row_major);
            }
        }
}

// ---------------------------------------------------------------------------
// Flash attention on mma.sync; 128 threads (4 warps), 64-row q tiles,
// double-buffered K/V, 2 blocks co-resident per SM.
// Buffer layout (halves): Khi[0,4608) Klo[4608,9216) Vhi[9216,13824) Vlo[13824,18432)
// ---------------------------------------------------------------------------
#define KP 72
#define BUF_H 18432
#define FA_SMEM (2 * BUF_H * 2 + 2048)

__global__ __launch_bounds__(128, 2)
void fa_kernel(const float* __restrict__ attn_bias)
{
    extern __shared__ char fsh[];
    __nv_bfloat16* sA    = (__nv_bfloat16*)fsh;
    float*         sbias = (float*)(fsh + 2 * BUF_H * 2);   // [8][64]

    const int bh = blockIdx.y;
    const int h  = bh & (NH - 1);
    const int b_ = bh >> 3;
    const int qtb = (int)(gridDim.x - 1) - (int)blockIdx.x;  // heavy first
    const int qt0 = qtb * 64;
    const int tid = threadIdx.x;
    const int w   = tid >> 5, lane = tid & 31;
    const int gid = lane >> 2, tig = lane & 3;

    const float* qg = g_q + (size_t)bh * T_SEQ * HDIM + (size_t)qt0 * HDIM;
    const __nv_bfloat16* khg = g_khi + (size_t)bh * T_SEQ * HDIM;
    const __nv_bfloat16* klg = g_klo + (size_t)bh * T_SEQ * HDIM;
    const __nv_bfloat16* vhg = g_vhi + (size_t)bh * HDIM * T_SEQ;
    const __nv_bfloat16* vlg = g_vlo + (size_t)bh * HDIM * T_SEQ;

    // ---- stage Q (64 x 64) hi/lo into buffer 0 ----
    for (int i = tid; i < 64 * 16; i += 128) {
        int row = i >> 4, c4 = (i & 15) * 4;
        float4 v = *(const float4*)&qg[(size_t)row * HDIM + c4];
        float f[4] = {v.x, v.y, v.z, v.w};
        __nv_bfloat16 hh[4], ll[4];
        split4(f, hh, ll);
#pragma unroll
        for (int j = 0; j < 4; j++) {
            sA[row * KP + c4 + j]        = hh[j];
            sA[4608 + row * KP + c4 + j] = ll[j];
        }
    }
    if (qtb < 8) {
        const float* bsrc = attn_bias + h * 64 * 64 + (qtb * 8) * 64;
        for (int i = tid; i < 8 * 64; i += 128) sbias[i] = bsrc[i];
    }
    __syncthreads();

    // ---- Q fragments (resident) ----
    uint32_t qh[4][4], ql[4][4];
    const int qrl = w * 16 + gid;
#pragma unroll
    for (int ks = 0; ks < 4; ks++) {
        int ad = qrl * KP + ks * 16 + 2 * tig;
        qh[ks][0] = *(const uint32_t*)&sA[ad];
        qh[ks][1] = *(const uint32_t*)&sA[ad + 8 * KP];
        qh[ks][2] = *(const uint32_t*)&sA[ad + 8];
        qh[ks][3] = *(const uint32_t*)&sA[ad + 8 * KP + 8];
        ql[ks][0] = *(const uint32_t*)&sA[4608 + ad];
        ql[ks][1] = *(const uint32_t*)&sA[4608 + ad + 8 * KP];
        ql[ks][2] = *(const uint32_t*)&sA[4608 + ad + 8];
        ql[ks][3] = *(const uint32_t*)&sA[4608 + ad + 8 * KP + 8];
    }
    __syncthreads();   // Q extracted; smem reused for K/V double buffer

    const int ktmax = qtb;

    // stage tile kt into buffer: 1 thread per row (64 K rows + 64 V d-rows)
    {
        const int kt = 0;
        if (tid < 64) {
            size_t s = (size_t)(kt * 64 + tid) * HDIM;
            int d0 = tid * KP;
#pragma unroll
            for (int e = 0; e < 8; e++) {
                *(uint4*)&sA[d0 + e * 8]        = *(const uint4*)&khg[s + e * 8];
                *(uint4*)&sA[4608 + d0 + e * 8] = *(const uint4*)&klg[s + e * 8];
            }
        } else {
            int d = tid - 64;
            size_t s = (size_t)d * T_SEQ + kt * 64;
            int d0 = 9216 + d * KP;
#pragma unroll
            for (int e = 0; e < 8; e++) {
                *(uint4*)&sA[d0 + e * 8]        = *(const uint4*)&vhg[s + e * 8];
                *(uint4*)&sA[4608 + d0 + e * 8] = *(const uint4*)&vlg[s + e * 8];
            }
        }
    }
    __syncthreads();

    float m0 = -1e30f, m1 = -1e30f, l0 = 0.f, l1 = 0.f;
    float oacc[8][4] = {};
    const int qr0 = qt0 + w * 16 + gid;
    const int qr1 = qr0 + 8;

    for (int kt = 0; kt <= ktmax; kt++) {
        // prefetch tile kt+1 into other buffer
        if (kt < ktmax) {
            const int nk = kt + 1;
            const int bo = (nk & 1) ? BUF_H : 0;
            if (tid < 64) {
                size_t s = (size_t)(nk * 64 + tid) * HDIM;
                int d0 = bo + tid * KP;
#pragma unroll
                for (int e = 0; e < 8; e++) {
                    *(uint4*)&sA[d0 + e * 8]        = *(const uint4*)&khg[s + e * 8];
                    *(uint4*)&sA[4608 + d0 + e * 8] = *(const uint4*)&klg[s + e * 8];
                }
            } else {
                int d = tid - 64;
                size_t s = (size_t)d * T_SEQ + nk * 64;
                int d0 = bo + 9216 + d * KP;
#pragma unroll
                for (int e = 0; e < 8; e++) {
                    *(uint4*)&sA[d0 + e * 8]        = *(const uint4*)&vhg[s + e * 8];
                    *(uint4*)&sA[4608 + d0 + e * 8] = *(const uint4*)&vlg[s + e * 8];
                }
            }
        }

        if (kt * 64 <= qt0 + w * 16 + 15) {   // strip not fully masked
            const __nv_bfloat16* skh = sA + ((kt & 1) ? BUF_H : 0);
            const __nv_bfloat16* skl = skh + 4608;
            const __nv_bfloat16* svh = skh + 9216;
            const __nv_bfloat16* svl = skh + 13824;

            // ---- S = Q K^T ----
            float sacc[8][4] = {};
#pragma unroll
            for (int nt = 0; nt < 8; nt++)
#pragma unroll
                for (int ks = 0; ks < 4; ks++) {
                    int ad = (nt * 8 + gid) * KP + ks * 16 + 2 * tig;
                    uint32_t bh0 = *(const uint32_t*)&skh[ad];
                    uint32_t bh1 = *(const uint32_t*)&skh[ad + 8];
                    uint32_t bl0 = *(const uint32_t*)&skl[ad];
                    uint32_t bl1 = *(const uint32_t*)&skl[ad + 8];
                    mma_bf16(sacc[nt], qh[ks], bh0, bh1);
                    mma_bf16(sacc[nt], qh[ks], bl0, bl1);
                    mma_bf16(sacc[nt], ql[ks], bh0, bh1);
                }

            // ---- scale + bias + masks ----
#pragma unroll
            for (int nt = 0; nt < 8; nt++) {
                float bb0 = 0.f, bb1 = 0.f;
                if (qtb < 8) {
                    bb0 = sbias[(2 * w) * 64 + kt * 8 + nt];
                    bb1 = sbias[(2 * w + 1) * 64 + kt * 8 + nt];
                }
#pragma unroll
                for (int c = 0; c < 4; c++) {
                    int kcol = kt * 64 + nt * 8 + 2 * tig + (c & 1);
                    int qr   = (c < 2) ? qr0 : qr1;
                    float s  = sacc[nt][c] * SCALE_F + ((c < 2) ? bb0 : bb1);
                    if (kcol > qr || (kcol & 15) == 15) s = -1e30f;
                    sacc[nt][c] = s;
                }
            }

            // ---- online softmax ----
            float rm0 = -1e30f, rm1 = -1e30f;
#pragma unroll
            for (int nt = 0; nt < 8; nt++) {
                rm0 = fmaxf(rm0, fmaxf(sacc[nt][0], sacc[nt][1]));
                rm1 = fmaxf(rm1, fmaxf(sacc[nt][2], sacc[nt][3]));
            }
            rm0 = fmaxf(rm0, __shfl_xor_sync(0xffffffffu, rm0, 1));
            rm0 = fmaxf(rm0, __shfl_xor_sync(0xffffffffu, rm0, 2));
            rm1 = fmaxf(rm1, __shfl_xor_sync(0xffffffffu, rm1, 1));
            rm1 = fmaxf(rm1, __shfl_xor_sync(0xffffffffu, rm1, 2));
            float mn0 = fmaxf(m0, rm0), mn1 = fmaxf(m1, rm1);
            float a0 = __expf(m0 - mn0), a1 = __expf(m1 - mn1);
            float rs0 = 0.f, rs1 = 0.f;
#pragma unroll
            for (int nt = 0; nt < 8; nt++) {
                sacc[nt][0] = __expf(sacc[nt][0] - mn0);
                sacc[nt][1] = __expf(sacc[nt][1] - mn0);
                sacc[nt][2] = __expf(sacc[nt][2] - mn1);
                sacc[nt][3] = __expf(sacc[nt][3] - mn1);
                rs0 += sacc[nt][0] + sacc[nt][1];
                rs1 += sacc[nt][2] + sacc[nt][3];
            }
            rs0 += __shfl_xor_sync(0xffffffffu, rs0, 1);
            rs0 += __shfl_xor_sync(0xffffffffu, rs0, 2);
            rs1 += __shfl_xor_sync(0xffffffffu, rs1, 1);
            rs1 += __shfl_xor_sync(0xffffffffu, rs1, 2);
            l0 = l0 * a0 + rs0; m0 = mn0;
            l1 = l1 * a1 + rs1; m1 = mn1;
#pragma unroll
            for (int dt = 0; dt < 8; dt++) {
                oacc[dt][0] *= a0; oacc[dt][1] *= a0;
                oacc[dt][2] *= a1; oacc[dt][3] *= a1;
            }

            // ---- P -> A-fragments from S accumulators (hi/lo) ----
            uint32_t ph[4][4], pl[4][4];
#pragma unroll
            for (int ks = 0; ks < 4; ks++)
#pragma unroll
                for (int half = 0; half < 2; half++) {
                    int nt = 2 * ks + half;
#pragma unroll
                    for (int rr = 0; rr < 2; rr++) {
                        float pe = sacc[nt][rr * 2 + 0];
                        float po = sacc[nt][rr * 2 + 1];
                        float he = __bfloat162float(__float2bfloat16(pe));
                        float ho = __bfloat162float(__float2bfloat16(po));
                        ph[ks][half * 2 + rr] = pack_bf2(he, ho);
                        pl[ks][half * 2 + rr] = pack_bf2(pe - he, po - ho);
                    }
                }

            // ---- O += P V ----
#pragma unroll
            for (int dt = 0; dt < 8; dt++)
#pragma unroll
                for (int ks = 0; ks < 4; ks++) {
                    int ad = (dt * 8 + gid) * KP + ks * 16 + 2 * tig;
                    uint32_t vh0 = *(const uint32_t*)&svh[ad];
                    uint32_t vh1 = *(const uint32_t*)&svh[ad + 8];
                    uint32_t vl0 = *(const uint32_t*)&svl[ad];
                    uint32_t vl1 = *(const uint32_t*)&svl[ad + 8];
                    mma_bf16(oacc[dt], ph[ks], vh0, vh1);
                    mma_bf16(oacc[dt], ph[ks], vl0, vl1);
                    mma_bf16(oacc[dt], pl[ks], vh0, vh1);
                }
        }
        __syncthreads();
    }

    // ---- epilogue: write y split (bf16 hi/lo) directly ----
    float inv0 = 1.0f / l0, inv1 = 1.0f / l1;
#pragma unroll
    for (int dt = 0; dt < 8; dt++) {
        int dcol = h * 64 + dt * 8 + 2 * tig;
        float y00 = oacc[dt][0] * inv0, y01 = oacc[dt][1] * inv0;
        float y10 = oacc[dt][2] * inv1, y11 = oacc[dt][3] * inv1;
        float h00 = __bfloat162float(__float2bfloat16(y00));
        float h01 = __bfloat162float(__float2bfloat16(y01));
        float h10 = __bfloat162float(__float2bfloat16(y10));
        float h11 = __bfloat162float(__float2bfloat16(y11));
        size_t i0 = ((size_t)(b_ * T_SEQ + qr0)) * CDIM + dcol;
        size_t i1 = ((size_t)(b_ * T_SEQ + qr1)) * CDIM + dcol;
        *(uint32_t*)&g_yhi[i0] = pack_bf2(h00, h01);
        *(uint32_t*)&g_ylo[i0] = pack_bf2(y00 - h00, y01 - h01);
        *(uint32_t*)&g_yhi[i1] = pack_bf2(h10, h11);
        *(uint32_t*)&g_ylo[i1] = pack_bf2(y10 - h10, y11 - h11);
    }
}

// ---------------------------------------------------------------------------

extern "C" void kernel_launch(void* const* d_in, const int* in_sizes, int n_in,
                              void* d_out, int out_size)
{
    const float* x  = (const float*)d_in[0];
    const float* ab = (const float*)d_in[1];
    const float* Wq = (const float*)d_in[2];
    const float* bq = (const float*)d_in[3];
    const float* Wk = (const float*)d_in[4];
    const float* bk = (const float*)d_in[5];
    const float* Wv = (const float*)d_in[6];
    const float* bv = (const float*)d_in[7];
    const float* Wp = (const float*)d_in[8];
    const float* bp = (const float*)d_in[9];
    float* out = (float*)d_out;

    // bf16 hi/lo conversions
    convert_x<<<(BATCH * T_SEQ * CDIM) / 1024, 256>>>(x);
    convert_w4<<<dim3((CDIM * CDIM) / 1024, 4), 256>>>(Wq, Wk, Wv, Wp);

    // QKV projections (wmma, 128x128 tiles)
    hm_gemm<0><<<dim3(CDIM / 128, (BATCH * T_SEQ) / 128, 3), 256>>>(bq, bk, bv, nullptr);

    // Pre-convert K/V to MMA-ready bf16 (V transposed)
    convert_kv<<<dim3(T_SEQ / 64, BATCH * NH), 256>>>();

    // Flash attention (mma.sync, 64-row q tiles, 2 blocks/SM)
    cudaFuncSetAttribute(fa_kernel, cudaFuncAttributeMaxDynamicSharedMemorySize,
                         FA_SMEM);
    fa_kernel<<<dim3(T_SEQ / 64, BATCH * NH), 128, FA_SMEM>>>(ab);

    // Output projection
    hm_gemm<1><<<dim3(CDIM / 128, (BATCH * T_SEQ) / 128, 1), 256>>>(bp, nullptr, nullptr, out);
}

// round 15
// speedup vs baseline: 1.0920x; 1.0920x over previous
#include <cuda_runtime.h>
#include <cuda_bf16.h>
#include <mma.h>
#include <cstdint>

using namespace nvcuda;

#define BATCH 4
#define T_SEQ 1024
#define CDIM  512
#define NH    8
#define HDIM  64
#define SCALE_F 0.125f

// ---------------------------------------------------------------------------
// Scratch (no cudaMalloc allowed). Referenced ONLY from device code.
// ---------------------------------------------------------------------------
__device__ __align__(16) float g_q[BATCH * NH * T_SEQ * HDIM];
__device__ __align__(16) float g_k[BATCH * NH * T_SEQ * HDIM];
__device__ __align__(16) float g_v[BATCH * NH * T_SEQ * HDIM];

__device__ __align__(16) __nv_bfloat16 g_xhi[BATCH * T_SEQ * CDIM];
__device__ __align__(16) __nv_bfloat16 g_xlo[BATCH * T_SEQ * CDIM];
__device__ __align__(16) __nv_bfloat16 g_whi[4 * CDIM * CDIM];
__device__ __align__(16) __nv_bfloat16 g_wlo[4 * CDIM * CDIM];
__device__ __align__(16) __nv_bfloat16 g_yhi[BATCH * T_SEQ * CDIM];
__device__ __align__(16) __nv_bfloat16 g_ylo[BATCH * T_SEQ * CDIM];

// K/V in MMA-ready bf16 hi/lo form; V pre-transposed [bh][d][t]
__device__ __align__(16) __nv_bfloat16 g_khi[BATCH * NH * T_SEQ * HDIM];
__device__ __align__(16) __nv_bfloat16 g_klo[BATCH * NH * T_SEQ * HDIM];
__device__ __align__(16) __nv_bfloat16 g_vhi[BATCH * NH * HDIM * T_SEQ];
__device__ __align__(16) __nv_bfloat16 g_vlo[BATCH * NH * HDIM * T_SEQ];

// ---------------------------------------------------------------------------
// helpers
// ---------------------------------------------------------------------------
__device__ __forceinline__ void split4(const float* f, __nv_bfloat16* h,
                                       __nv_bfloat16* l) {
#pragma unroll
    for (int j = 0; j < 4; j++) {
        h[j] = __float2bfloat16(f[j]);
        l[j] = __float2bfloat16(f[j] - __bfloat162float(h[j]));
    }
}

__device__ __forceinline__ void mma_bf16(float* d, const uint32_t* a,
                                         uint32_t b0, uint32_t b1) {
    asm volatile(
        "mma.sync.aligned.m16n8k16.row.col.f32.bf16.bf16.f32 "
        "{%0,%1,%2,%3}, {%4,%5,%6,%7}, {%8,%9}, {%0,%1,%2,%3};"
        : "+f"(d[0]), "+f"(d[1]), "+f"(d[2]), "+f"(d[3])
        : "r"(a[0]), "r"(a[1]), "r"(a[2]), "r"(a[3]), "r"(b0), "r"(b1));
}

__device__ __forceinline__ uint32_t pack_bf2(float lo, float hi) {
    __nv_bfloat162 t = __floats2bfloat162_rn(lo, hi);  // .x = low 16 bits
    return *(uint32_t*)&t;
}

__device__ __forceinline__ uint32_t smem_u32(const void* p) {
    return (uint32_t)__cvta_generic_to_shared(p);
}

__device__ __forceinline__ void cp_async16(uint32_t dst, const void* src) {
    asm volatile("cp.async.ca.shared.global [%0], [%1], 16;"
                 :: "r"(dst), "l"(src));
}
#define CP_COMMIT() asm volatile("cp.async.commit_group;")
#define CP_WAIT1()  asm volatile("cp.async.wait_group 1;")

// ---------------------------------------------------------------------------
// fp32 -> bf16 hi/lo split conversions
// ---------------------------------------------------------------------------
__global__ __launch_bounds__(256)
void convert_x(const float* __restrict__ src)
{
    int i = (blockIdx.x * 256 + threadIdx.x) * 4;
    float4 v = *(const float4*)(src + i);
    float f[4] = {v.x, v.y, v.z, v.w};
    __nv_bfloat16 h[4], l[4];
    split4(f, h, l);
    *(uint2*)(g_xhi + i) = *(uint2*)h;
    *(uint2*)(g_xlo + i) = *(uint2*)l;
}

__global__ __launch_bounds__(256)
void convert_w4(const float* __restrict__ w0, const float* __restrict__ w1,
                const float* __restrict__ w2, const float* __restrict__ w3)
{
    int z = blockIdx.y;
    const float* src = (z == 0) ? w0 : (z == 1) ? w1 : (z == 2) ? w2 : w3;
    int i = (blockIdx.x * 256 + threadIdx.x) * 4;
    float4 v = *(const float4*)(src + i);
    float f[4] = {v.x, v.y, v.z, v.w};
    __nv_bfloat16 h[4], l[4];
    split4(f, h, l);
    size_t o = (size_t)z * CDIM * CDIM + i;
    *(uint2*)(g_whi + o) = *(uint2*)h;
    *(uint2*)(g_wlo + o) = *(uint2*)l;
}

// K -> khi/klo [bh][t][d];  V -> vhi/vlo transposed [bh][d][t]
__global__ __launch_bounds__(256)
void convert_kv()
{
    __shared__ float vt[64][68];

    const int bh = blockIdx.y;
    const int t0 = blockIdx.x * 64;
    const int tid = threadIdx.x;
    const size_t base = (size_t)bh * T_SEQ * HDIM;

    for (int i = tid; i < 64 * 16; i += 256) {
        int row = i >> 4, c4 = (i & 15) * 4;
        size_t idx = base + (size_t)(t0 + row) * HDIM + c4;
        float4 v = *(const float4*)&g_k[idx];
        float f[4] = {v.x, v.y, v.z, v.w};
        __nv_bfloat16 h[4], l[4];
        split4(f, h, l);
        *(uint2*)(g_khi + idx) = *(uint2*)h;
        *(uint2*)(g_klo + idx) = *(uint2*)l;
        float4 vv = *(const float4*)&g_v[idx];
        vt[row][c4 + 0] = vv.x; vt[row][c4 + 1] = vv.y;
        vt[row][c4 + 2] = vv.z; vt[row][c4 + 3] = vv.w;
    }
    __syncthreads();

    for (int i = tid; i < 64 * 16; i += 256) {
        int d = i >> 4, tq = (i & 15) * 4;
        float f[4] = {vt[tq][d], vt[tq + 1][d], vt[tq + 2][d], vt[tq + 3][d]};
        __nv_bfloat16 h[4], l[4];
        split4(f, h, l);
        size_t idx = (size_t)bh * HDIM * T_SEQ + (size_t)d * T_SEQ + t0 + tq;
        *(uint2*)(g_vhi + idx) = *(uint2*)h;
        *(uint2*)(g_vlo + idx) = *(uint2*)l;
    }
}

// ---------------------------------------------------------------------------
// Projection GEMMs via wmma, 128x128 tile, BK=32, 256 threads.
// 3-stage cp.async pipeline, ONE __syncthreads per kt.
// Stage layout (halves): Ahi[0,5120) Alo[5120,10240) Bhi Blo; pitch GP=40.
// ---------------------------------------------------------------------------
#define GP 40
#define MATH 5120
#define STG_H (4 * MATH)                 // halves per stage
#define GEMM_SMEM (3 * STG_H * 2)        // bytes (122880)

template <int MODE>
__global__ __launch_bounds__(256, 1)
void hm_gemm(const float* __restrict__ bias0, const float* __restrict__ bias1,
             const float* __restrict__ bias2, float* __restrict__ out_proj)
{
    extern __shared__ __align__(16) __nv_bfloat16 dsm[];   // 3 stages
    __shared__ __align__(16) float sbias[16 * 132];

    const int tid = threadIdx.x;
    const int wid = tid >> 5;
    const int wm = wid >> 2, wn = wid & 3;

    const int n0 = blockIdx.x * 128;
    const int m0 = blockIdx.y * 128;
    const int z  = (MODE == 0) ? (int)blockIdx.z : 3;

    const float* bias = (MODE == 0) ? ((z == 0) ? bias0 : (z == 1) ? bias1 : bias2)
                                    : bias0;
    float* outp = (MODE == 0) ? ((z == 0) ? g_q : (z == 1) ? g_k : g_v) : out_proj;

    const __nv_bfloat16* Ahi = ((MODE == 0) ? g_xhi : g_yhi) + (size_t)m0 * CDIM;
    const __nv_bfloat16* Alo = ((MODE == 0) ? g_xlo : g_ylo) + (size_t)m0 * CDIM;
    const __nv_bfloat16* Bhi = g_whi + (size_t)z * CDIM * CDIM + (size_t)n0 * CDIM;
    const __nv_bfloat16* Blo = g_wlo + (size_t)z * CDIM * CDIM + (size_t)n0 * CDIM;
    const __nv_bfloat16* srcs[4] = {Ahi, Alo, Bhi, Blo};

    for (int idx = tid; idx < 16 * 128; idx += 256) {
        int r = idx >> 7, c = idx & 127;
        sbias[r * 132 + c] = bias[n0 + c];
    }

    // loader: 256 threads, 2 x 16B per thread per matrix (128 rows x 32 halves)
    const int lr0 = tid >> 1;
    const int lq0 = (tid & 1) * 2;
    const uint32_t dsm_b = smem_u32(dsm);

    // prologue: stages for kt=0,1
#pragma unroll
    for (int s = 0; s < 2; s++) {
        uint32_t sb = dsm_b + s * STG_H * 2;
#pragma unroll
        for (int mat = 0; mat < 4; mat++)
#pragma unroll
            for (int e = 0; e < 2; e++)
                cp_async16(sb + (mat * MATH + lr0 * GP + (lq0 + e) * 8) * 2,
                           srcs[mat] + (size_t)lr0 * CDIM + s * 32 + (lq0 + e) * 8);
        CP_COMMIT();
    }

    wmma::fragment<wmma::accumulator, 16, 16, 16, float> acc[4][2];
    __syncthreads();  // sbias visible
#pragma unroll
    for (int mi = 0; mi < 4; mi++)
#pragma unroll
        for (int ni = 0; ni < 2; ni++)
            wmma::load_matrix_sync(acc[mi][ni], &sbias[wn * 32 + ni * 16], 132,
                                   wmma::mem_row_major);

    for (int kt = 0; kt < CDIM / 32; kt++) {
        CP_WAIT1();
        __syncthreads();   // stage kt ready for all warps

        const __nv_bfloat16* sm = dsm + (kt % 3) * STG_H;
#pragma unroll
        for (int ks = 0; ks < 2; ks++) {
            wmma::fragment<wmma::matrix_a, 16, 16, 16, __nv_bfloat16, wmma::row_major> fah[4], fal[4];
            wmma::fragment<wmma::matrix_b, 16, 16, 16, __nv_bfloat16, wmma::col_major> fbh[2], fbl[2];
#pragma unroll
            for (int mi = 0; mi < 4; mi++) {
                int mr = wm * 64 + mi * 16;
                wmma::load_matrix_sync(fah[mi], &sm[0 * MATH + mr * GP + ks * 16], GP);
                wmma::load_matrix_sync(fal[mi], &sm[1 * MATH + mr * GP + ks * 16], GP);
            }
#pragma unroll
            for (int ni = 0; ni < 2; ni++) {
                int nr = wn * 32 + ni * 16;
                wmma::load_matrix_sync(fbh[ni], &sm[2 * MATH + nr * GP + ks * 16], GP);
                wmma::load_matrix_sync(fbl[ni], &sm[3 * MATH + nr * GP + ks * 16], GP);
            }
#pragma unroll
            for (int mi = 0; mi < 4; mi++)
#pragma unroll
                for (int ni = 0; ni < 2; ni++) {
                    wmma::mma_sync(acc[mi][ni], fah[mi], fbh[ni], acc[mi][ni]);
                    wmma::mma_sync(acc[mi][ni], fah[mi], fbl[ni], acc[mi][ni]);
                    wmma::mma_sync(acc[mi][ni], fal[mi], fbh[ni], acc[mi][ni]);
                }
        }

        // prefetch kt+2 into stage (kt+2)%3 (read by compute(kt-1), which all
        // warps finished before this iteration's barrier)
        if (kt + 2 < CDIM / 32) {
            uint32_t sb = dsm_b + ((kt + 2) % 3) * STG_H * 2;
            int k0 = (kt + 2) * 32;
#pragma unroll
            for (int mat = 0; mat < 4; mat++)
#pragma unroll
                for (int e = 0; e < 2; e++)
                    cp_async16(sb + (mat * MATH + lr0 * GP + (lq0 + e) * 8) * 2,
                               srcs[mat] + (size_t)lr0 * CDIM + k0 + (lq0 + e) * 8);
        }
        CP_COMMIT();   // empty group when nothing issued keeps counts aligned
    }

    // epilogue: each 16-col tile lies within one head (offsets multiple of 16)
#pragma unroll
    for (int mi = 0; mi < 4; mi++)
#pragma unroll
        for (int ni = 0; ni < 2; ni++) {
            int m = m0 + wm * 64 + mi * 16;
            int n = n0 + wn * 32 + ni * 16;
            if (MODE == 0) {
                int b_ = m >> 10;
                int t0 = m & 1023;
                int h  = n >> 6;
                int d0 = n & 63;
                float* dst = &outp[(((size_t)(b_ * NH + h)) * T_SEQ + t0) * HDIM + d0];
                wmma::store_matrix_sync(dst, acc[mi][ni], HDIM, wmma::mem_row_major);
            } else {
                wmma::store_matrix_sync(&outp[(size_t)m * CDIM + n], acc[mi][ni],
                                        CDIM, wmma::mem_row_major);
            }
        }
}

// ---------------------------------------------------------------------------
// Flash attention on mma.sync (exact R13 passing version: 256 threads,
// 128-row q tiles, double-buffered K/V)
// ---------------------------------------------------------------------------
#define KP 72
#define BUF_H 18432
#define FA_SMEM (2 * BUF_H * 2 + 4096)

__global__ __launch_bounds__(256, 1)
void fa_kernel(const float* __restrict__ attn_bias)
{
    extern __shared__ char fsh[];
    __nv_bfloat16* sA    = (__nv_bfloat16*)fsh;
    float*         sbias = (float*)(fsh + 2 * BUF_H * 2);

    const int bh = blockIdx.y;
    const int h  = bh & (NH - 1);
    const int b_ = bh >> 3;
    const int qt = (int)(gridDim.x - 1) - (int)blockIdx.x;
    const int tid = threadIdx.x;
    const int w   = tid >> 5, lane = tid & 31;
    const int gid = lane >> 2, tig = lane & 3;

    const float* qg = g_q + (size_t)bh * T_SEQ * HDIM + (size_t)qt * 128 * HDIM;
    const __nv_bfloat16* khg = g_khi + (size_t)bh * T_SEQ * HDIM;
    const __nv_bfloat16* klg = g_klo + (size_t)bh * T_SEQ * HDIM;
    const __nv_bfloat16* vhg = g_vhi + (size_t)bh * HDIM * T_SEQ;
    const __nv_bfloat16* vlg = g_vlo + (size_t)bh * HDIM * T_SEQ;

    for (int i = tid; i < 128 * 16; i += 256) {
        int row = i >> 4, c4 = (i & 15) * 4;
        float4 v = *(const float4*)&qg[(size_t)row * HDIM + c4];
        float f[4] = {v.x, v.y, v.z, v.w};
        __nv_bfloat16 hh[4], ll[4];
        split4(f, hh, ll);
#pragma unroll
        for (int j = 0; j < 4; j++) {
            sA[row * KP + c4 + j]        = hh[j];
            sA[9216 + row * KP + c4 + j] = ll[j];
        }
    }
    if (qt < 4) {
        const float* bsrc = attn_bias + h * 64 * 64 + (qt * 16) * 64;
        for (int i = tid; i < 16 * 64; i += 256) sbias[i] = bsrc[i];
    }
    __syncthreads();

    uint32_t qh[4][4], ql[4][4];
    const int qrl = w * 16 + gid;
#pragma unroll
    for (int ks = 0; ks < 4; ks++) {
        int ad = qrl * KP + ks * 16 + 2 * tig;
        qh[ks][0] = *(const uint32_t*)&sA[ad];
        qh[ks][1] = *(const uint32_t*)&sA[ad + 8 * KP];
        qh[ks][2] = *(const uint32_t*)&sA[ad + 8];
        qh[ks][3] = *(const uint32_t*)&sA[ad + 8 * KP + 8];
        ql[ks][0] = *(const uint32_t*)&sA[9216 + ad];
        ql[ks][1] = *(const uint32_t*)&sA[9216 + ad + 8 * KP];
        ql[ks][2] = *(const uint32_t*)&sA[9216 + ad + 8];
        ql[ks][3] = *(const uint32_t*)&sA[9216 + ad + 8 * KP + 8];
    }
    __syncthreads();

    const int ktmax = 2 * qt + 1;
    const int crow = tid >> 1;
    const int cseg = (tid & 1) * 4;

    {
        const int kt = 0;
        __nv_bfloat16* dst = sA;
        const __nv_bfloat16* shi = (crow < 64) ? khg : (vhg - 64 * T_SEQ);
        const __nv_bfloat16* slo = (crow < 64) ? klg : (vlg - 64 * T_SEQ);
        int row = crow & 63;
        size_t soff = (crow < 64) ? ((size_t)(kt * 64 + row) * HDIM)
                                  : ((size_t)(crow) * T_SEQ + kt * 64);
        int doff = ((crow < 64) ? 0 : 9216) + row * KP;
#pragma unroll
        for (int e = 0; e < 4; e++) {
            *(uint4*)&dst[doff + (cseg + e) * 8] =
                *(const uint4*)&shi[soff + (cseg + e) * 8];
            *(uint4*)&dst[4608 + doff + (cseg + e) * 8] =
                *(const uint4*)&slo[soff + (cseg + e) * 8];
        }
    }
    __syncthreads();

    float m0 = -1e30f, m1 = -1e30f, l0 = 0.f, l1 = 0.f;
    float oacc[8][4] = {};
    const int qr0 = qt * 128 + w * 16 + gid;
    const int qr1 = qr0 + 8;

    for (int kt = 0; kt <= ktmax; kt++) {
        if (kt < ktmax) {
            const int nk = kt + 1;
            __nv_bfloat16* dst = sA + ((nk & 1) ? BUF_H : 0);
            const __nv_bfloat16* shi = (crow < 64) ? khg : (vhg - 64 * T_SEQ);
            const __nv_bfloat16* slo = (crow < 64) ? klg : (vlg - 64 * T_SEQ);
            int row = crow & 63;
            size_t soff = (crow < 64) ? ((size_t)(nk * 64 + row) * HDIM)
                                      : ((size_t)(crow) * T_SEQ + nk * 64);
            int doff = ((crow < 64) ? 0 : 9216) + row * KP;
#pragma unroll
            for (int e = 0; e < 4; e++) {
                *(uint4*)&dst[doff + (cseg + e) * 8] =
                    *(const uint4*)&shi[soff + (cseg + e) * 8];
                *(uint4*)&dst[4608 + doff + (cseg + e) * 8] =
                    *(const uint4*)&slo[soff + (cseg + e) * 8];
            }
        }

        if (kt * 64 <= qt * 128 + w * 16 + 15) {
            const __nv_bfloat16* skh = sA + ((kt & 1) ? BUF_H : 0);
            const __nv_bfloat16* skl = skh + 4608;
            const __nv_bfloat16* svh = skh + 9216;
            const __nv_bfloat16* svl = skh + 13824;

            float sacc[8][4] = {};
#pragma unroll
            for (int nt = 0; nt < 8; nt++)
#pragma unroll
                for (int ks = 0; ks < 4; ks++) {
                    int ad = (nt * 8 + gid) * KP + ks * 16 + 2 * tig;
                    uint32_t bh0 = *(const uint32_t*)&skh[ad];
                    uint32_t bh1 = *(const uint32_t*)&skh[ad + 8];
                    uint32_t bl0 = *(const uint32_t*)&skl[ad];
                    uint32_t bl1 = *(const uint32_t*)&skl[ad + 8];
                    mma_bf16(sacc[nt], qh[ks], bh0, bh1);
                    mma_bf16(sacc[nt], qh[ks], bl0, bl1);
                    mma_bf16(sacc[nt], ql[ks], bh0, bh1);
                }

#pragma unroll
            for (int nt = 0; nt < 8; nt++) {
                float bb0 = 0.f, bb1 = 0.f;
                if (qt < 4) {
                    bb0 = sbias[(2 * w) * 64 + kt * 8 + nt];
                    bb1 = sbias[(2 * w + 1) * 64 + kt * 8 + nt];
                }
#pragma unroll
                for (int c = 0; c < 4; c++) {
                    int kcol = kt * 64 + nt * 8 + 2 * tig + (c & 1);
                    int qr   = (c < 2) ? qr0 : qr1;
                    float s  = sacc[nt][c] * SCALE_F + ((c < 2) ? bb0 : bb1);
                    if (kcol > qr || (kcol & 15) == 15) s = -1e30f;
                    sacc[nt][c] = s;
                }
            }

            float rm0 = -1e30f, rm1 = -1e30f;
#pragma unroll
            for (int nt = 0; nt < 8; nt++) {
                rm0 = fmaxf(rm0, fmaxf(sacc[nt][0], sacc[nt][1]));
                rm1 = fmaxf(rm1, fmaxf(sacc[nt][2], sacc[nt][3]));
            }
            rm0 = fmaxf(rm0, __shfl_xor_sync(0xffffffffu, rm0, 1));
            rm0 = fmaxf(rm0, __shfl_xor_sync(0xffffffffu, rm0, 2));
            rm1 = fmaxf(rm1, __shfl_xor_sync(0xffffffffu, rm1, 1));
            rm1 = fmaxf(rm1, __shfl_xor_sync(0xffffffffu, rm1, 2));
            float mn0 = fmaxf(m0, rm0), mn1 = fmaxf(m1, rm1);
            float a0 = __expf(m0 - mn0), a1 = __expf(m1 - mn1);
            float rs0 = 0.f, rs1 = 0.f;
#pragma unroll
            for (int nt = 0; nt < 8; nt++) {
                sacc[nt][0] = __expf(sacc[nt][0] - mn0);
                sacc[nt][1] = __expf(sacc[nt][1] - mn0);
                sacc[nt][2] = __expf(sacc[nt][2] - mn1);
                sacc[nt][3] = __expf(sacc[nt][3] - mn1);
                rs0 += sacc[nt][0] + sacc[nt][1];
                rs1 += sacc[nt][2] + sacc[nt][3];
            }
            rs0 += __shfl_xor_sync(0xffffffffu, rs0, 1);
            rs0 += __shfl_xor_sync(0xffffffffu, rs0, 2);
            rs1 += __shfl_xor_sync(0xffffffffu, rs1, 1);
            rs1 += __shfl_xor_sync(0xffffffffu, rs1, 2);
            l0 = l0 * a0 + rs0; m0 = mn0;
            l1 = l1 * a1 + rs1; m1 = mn1;
#pragma unroll
            for (int dt = 0; dt < 8; dt++) {
                oacc[dt][0] *= a0; oacc[dt][1] *= a0;
                oacc[dt][2] *= a1; oacc[dt][3] *= a1;
            }

            uint32_t ph[4][4], pl[4][4];
#pragma unroll
            for (int ks = 0; ks < 4; ks++)
#pragma unroll
                for (int half = 0; half < 2; half++) {
                    int nt = 2 * ks + half;
#pragma unroll
                    for (int rr = 0; rr < 2; rr++) {
                        float pe = sacc[nt][rr * 2 + 0];
                        float po = sacc[nt][rr * 2 + 1];
                        float he = __bfloat162float(__float2bfloat16(pe));
                        float ho = __bfloat162float(__float2bfloat16(po));
                        ph[ks][half * 2 + rr] = pack_bf2(he, ho);
                        pl[ks][half * 2 + rr] = pack_bf2(pe - he, po - ho);
                    }
                }

#pragma unroll
            for (int dt = 0; dt < 8; dt++)
#pragma unroll
                for (int ks = 0; ks < 4; ks++) {
                    int ad = (dt * 8 + gid) * KP + ks * 16 + 2 * tig;
                    uint32_t vh0 = *(const uint32_t*)&svh[ad];
                    uint32_t vh1 = *(const uint32_t*)&svh[ad + 8];
                    uint32_t vl0 = *(const uint32_t*)&svl[ad];
                    uint32_t vl1 = *(const uint32_t*)&svl[ad + 8];
                    mma_bf16(oacc[dt], ph[ks], vh0, vh1);
                    mma_bf16(oacc[dt], ph[ks], vl0, vl1);
                    mma_bf16(oacc[dt], pl[ks], vh0, vh1);
                }
        }
        __syncthreads();
    }

    float inv0 = 1.0f / l0, inv1 = 1.0f / l1;
#pragma unroll
    for (int dt = 0; dt < 8; dt++) {
        int dcol = h * 64 + dt * 8 + 2 * tig;
        float y00 = oacc[dt][0] * inv0, y01 = oacc[dt][1] * inv0;
        float y10 = oacc[dt][2] * inv1, y11 = oacc[dt][3] * inv1;
        float h00 = __bfloat162float(__float2bfloat16(y00));
        float h01 = __bfloat162float(__float2bfloat16(y01));
        float h10 = __bfloat162float(__float2bfloat16(y10));
        float h11 = __bfloat162float(__float2bfloat16(y11));
        size_t i0 = ((size_t)(b_ * T_SEQ + qr0)) * CDIM + dcol;
        size_t i1 = ((size_t)(b_ * T_SEQ + qr1)) * CDIM + dcol;
        *(uint32_t*)&g_yhi[i0] = pack_bf2(h00, h01);
        *(uint32_t*)&g_ylo[i0] = pack_bf2(y00 - h00, y01 - h01);
        *(uint32_t*)&g_yhi[i1] = pack_bf2(h10, h11);
        *(uint32_t*)&g_ylo[i1] = pack_bf2(y10 - h10, y11 - h11);
    }
}

// ---------------------------------------------------------------------------

extern "C" void kernel_launch(void* const* d_in, const int* in_sizes, int n_in,
                              void* d_out, int out_size)
{
    const float* x  = (const float*)d_in[0];
    const float* ab = (const float*)d_in[1];
    const float* Wq = (const float*)d_in[2];
    const float* bq = (const float*)d_in[3];
    const float* Wk = (const float*)d_in[4];
    const float* bk = (const float*)d_in[5];
    const float* Wv = (const float*)d_in[6];
    const float* bv = (const float*)d_in[7];
    const float* Wp = (const float*)d_in[8];
    const float* bp = (const float*)d_in[9];
    float* out = (float*)d_out;

    // bf16 hi/lo conversions
    convert_x<<<(BATCH * T_SEQ * CDIM) / 1024, 256>>>(x);
    convert_w4<<<dim3((CDIM * CDIM) / 1024, 4), 256>>>(Wq, Wk, Wv, Wp);

    // QKV projections (wmma + cp.async pipeline)
    cudaFuncSetAttribute(hm_gemm<0>, cudaFuncAttributeMaxDynamicSharedMemorySize,
                         GEMM_SMEM);
    hm_gemm<0><<<dim3(CDIM / 128, (BATCH * T_SEQ) / 128, 3), 256, GEMM_SMEM>>>(
        bq, bk, bv, nullptr);

    // Pre-convert K/V to MMA-ready bf16 (V transposed)
    convert_kv<<<dim3(T_SEQ / 64, BATCH * NH), 256>>>();

    // Flash attention (mma.sync, 128-row q tiles — R13 proven config)
    cudaFuncSetAttribute(fa_kernel, cudaFuncAttributeMaxDynamicSharedMemorySize,
                         FA_SMEM);
    fa_kernel<<<dim3(T_SEQ / 128, BATCH * NH), 256, FA_SMEM>>>(ab);

    // Output projection
    cudaFuncSetAttribute(hm_gemm<1>, cudaFuncAttributeMaxDynamicSharedMemorySize,
                         GEMM_SMEM);
    hm_gemm<1><<<dim3(CDIM / 128, (BATCH * T_SEQ) / 128, 1), 256, GEMM_SMEM>>>(
        bp, nullptr, nullptr, out);
}

// round 17
// speedup vs baseline: 1.1127x; 1.0190x over previous
#include <cuda_runtime.h>
#include <cuda_bf16.h>
#include <mma.h>
#include <cstdint>

using namespace nvcuda;

#define BATCH 4
#define T_SEQ 1024
#define CDIM  512
#define NH    8
#define HDIM  64
#define SCALE_F 0.125f

// ---------------------------------------------------------------------------
// Scratch (no cudaMalloc allowed). Referenced ONLY from device code.
// ---------------------------------------------------------------------------
__device__ __align__(16) float g_q[BATCH * NH * T_SEQ * HDIM];
__device__ __align__(16) float g_k[BATCH * NH * T_SEQ * HDIM];
__device__ __align__(16) float g_v[BATCH * NH * T_SEQ * HDIM];

__device__ __align__(16) __nv_bfloat16 g_xhi[BATCH * T_SEQ * CDIM];
__device__ __align__(16) __nv_bfloat16 g_xlo[BATCH * T_SEQ * CDIM];
__device__ __align__(16) __nv_bfloat16 g_whi[4 * CDIM * CDIM];
__device__ __align__(16) __nv_bfloat16 g_wlo[4 * CDIM * CDIM];
__device__ __align__(16) __nv_bfloat16 g_yhi[BATCH * T_SEQ * CDIM];
__device__ __align__(16) __nv_bfloat16 g_ylo[BATCH * T_SEQ * CDIM];

// K/V in MMA-ready bf16 hi/lo form; V pre-transposed [bh][d][t]
__device__ __align__(16) __nv_bfloat16 g_khi[BATCH * NH * T_SEQ * HDIM];
__device__ __align__(16) __nv_bfloat16 g_klo[BATCH * NH * T_SEQ * HDIM];
__device__ __align__(16) __nv_bfloat16 g_vhi[BATCH * NH * HDIM * T_SEQ];
__device__ __align__(16) __nv_bfloat16 g_vlo[BATCH * NH * HDIM * T_SEQ];

// ---------------------------------------------------------------------------
// helpers
// ---------------------------------------------------------------------------
__device__ __forceinline__ void split4(const float* f, __nv_bfloat16* h,
                                       __nv_bfloat16* l) {
#pragma unroll
    for (int j = 0; j < 4; j++) {
        h[j] = __float2bfloat16(f[j]);
        l[j] = __float2bfloat16(f[j] - __bfloat162float(h[j]));
    }
}

__device__ __forceinline__ void mma_bf16(float* d, const uint32_t* a,
                                         uint32_t b0, uint32_t b1) {
    asm volatile(
        "mma.sync.aligned.m16n8k16.row.col.f32.bf16.bf16.f32 "
        "{%0,%1,%2,%3}, {%4,%5,%6,%7}, {%8,%9}, {%0,%1,%2,%3};"
        : "+f"(d[0]), "+f"(d[1]), "+f"(d[2]), "+f"(d[3])
        : "r"(a[0]), "r"(a[1]), "r"(a[2]), "r"(a[3]), "r"(b0), "r"(b1));
}

__device__ __forceinline__ void ldsm_x4(uint32_t* r, uint32_t addr) {
    asm volatile("ldmatrix.sync.aligned.m8n8.x4.shared.b16 {%0,%1,%2,%3}, [%4];"
                 : "=r"(r[0]), "=r"(r[1]), "=r"(r[2]), "=r"(r[3]) : "r"(addr));
}

__device__ __forceinline__ uint32_t pack_bf2(float lo, float hi) {
    __nv_bfloat162 t = __floats2bfloat162_rn(lo, hi);  // .x = low 16 bits
    return *(uint32_t*)&t;
}

__device__ __forceinline__ uint32_t smem_u32(const void* p) {
    return (uint32_t)__cvta_generic_to_shared(p);
}

__device__ __forceinline__ void cp_async16(uint32_t dst, const void* src) {
    asm volatile("cp.async.ca.shared.global [%0], [%1], 16;"
                 :: "r"(dst), "l"(src));
}
#define CP_COMMIT() asm volatile("cp.async.commit_group;")
#define CP_WAIT1()  asm volatile("cp.async.wait_group 1;")

// ---------------------------------------------------------------------------
// fp32 -> bf16 hi/lo split conversions
// ---------------------------------------------------------------------------
__global__ __launch_bounds__(256)
void convert_x(const float* __restrict__ src)
{
    int i = (blockIdx.x * 256 + threadIdx.x) * 4;
    float4 v = *(const float4*)(src + i);
    float f[4] = {v.x, v.y, v.z, v.w};
    __nv_bfloat16 h[4], l[4];
    split4(f, h, l);
    *(uint2*)(g_xhi + i) = *(uint2*)h;
    *(uint2*)(g_xlo + i) = *(uint2*)l;
}

__global__ __launch_bounds__(256)
void convert_w4(const float* __restrict__ w0, const float* __restrict__ w1,
                const float* __restrict__ w2, const float* __restrict__ w3)
{
    int z = blockIdx.y;
    const float* src = (z == 0) ? w0 : (z == 1) ? w1 : (z == 2) ? w2 : w3;
    int i = (blockIdx.x * 256 + threadIdx.x) * 4;
    float4 v = *(const float4*)(src + i);
    float f[4] = {v.x, v.y, v.z, v.w};
    __nv_bfloat16 h[4], l[4];
    split4(f, h, l);
    size_t o = (size_t)z * CDIM * CDIM + i;
    *(uint2*)(g_whi + o) = *(uint2*)h;
    *(uint2*)(g_wlo + o) = *(uint2*)l;
}

// K -> khi/klo [bh][t][d];  V -> vhi/vlo transposed [bh][d][t]
__global__ __launch_bounds__(256)
void convert_kv()
{
    __shared__ float vt[64][68];

    const int bh = blockIdx.y;
    const int t0 = blockIdx.x * 64;
    const int tid = threadIdx.x;
    const size_t base = (size_t)bh * T_SEQ * HDIM;

    for (int i = tid; i < 64 * 16; i += 256) {
        int row = i >> 4, c4 = (i & 15) * 4;
        size_t idx = base + (size_t)(t0 + row) * HDIM + c4;
        float4 v = *(const float4*)&g_k[idx];
        float f[4] = {v.x, v.y, v.z, v.w};
        __nv_bfloat16 h[4], l[4];
        split4(f, h, l);
        *(uint2*)(g_khi + idx) = *(uint2*)h;
        *(uint2*)(g_klo + idx) = *(uint2*)l;
        float4 vv = *(const float4*)&g_v[idx];
        vt[row][c4 + 0] = vv.x; vt[row][c4 + 1] = vv.y;
        vt[row][c4 + 2] = vv.z; vt[row][c4 + 3] = vv.w;
    }
    __syncthreads();

    for (int i = tid; i < 64 * 16; i += 256) {
        int d = i >> 4, tq = (i & 15) * 4;
        float f[4] = {vt[tq][d], vt[tq + 1][d], vt[tq + 2][d], vt[tq + 3][d]};
        __nv_bfloat16 h[4], l[4];
        split4(f, h, l);
        size_t idx = (size_t)bh * HDIM * T_SEQ + (size_t)d * T_SEQ + t0 + tq;
        *(uint2*)(g_vhi + idx) = *(uint2*)h;
        *(uint2*)(g_vlo + idx) = *(uint2*)l;
    }
}

// ---------------------------------------------------------------------------
// Projection GEMMs via wmma, 128x128 tile, BK=32, 256 threads.
// 3-stage cp.async pipeline (passing R15 version, unchanged)
// ---------------------------------------------------------------------------
#define GP 40
#define MATH 5120
#define STG_H (4 * MATH)
#define GEMM_SMEM (3 * STG_H * 2)

template <int MODE>
__global__ __launch_bounds__(256, 1)
void hm_gemm(const float* __restrict__ bias0, const float* __restrict__ bias1,
             const float* __restrict__ bias2, float* __restrict__ out_proj)
{
    extern __shared__ __align__(16) __nv_bfloat16 dsm[];
    __shared__ __align__(16) float sbias[16 * 132];

    const int tid = threadIdx.x;
    const int wid = tid >> 5;
    const int wm = wid >> 2, wn = wid & 3;

    const int n0 = blockIdx.x * 128;
    const int m0 = blockIdx.y * 128;
    const int z  = (MODE == 0) ? (int)blockIdx.z : 3;

    const float* bias = (MODE == 0) ? ((z == 0) ? bias0 : (z == 1) ? bias1 : bias2)
                                    : bias0;
    float* outp = (MODE == 0) ? ((z == 0) ? g_q : (z == 1) ? g_k : g_v) : out_proj;

    const __nv_bfloat16* Ahi = ((MODE == 0) ? g_xhi : g_yhi) + (size_t)m0 * CDIM;
    const __nv_bfloat16* Alo = ((MODE == 0) ? g_xlo : g_ylo) + (size_t)m0 * CDIM;
    const __nv_bfloat16* Bhi = g_whi + (size_t)z * CDIM * CDIM + (size_t)n0 * CDIM;
    const __nv_bfloat16* Blo = g_wlo + (size_t)z * CDIM * CDIM + (size_t)n0 * CDIM;
    const __nv_bfloat16* srcs[4] = {Ahi, Alo, Bhi, Blo};

    for (int idx = tid; idx < 16 * 128; idx += 256) {
        int r = idx >> 7, c = idx & 127;
        sbias[r * 132 + c] = bias[n0 + c];
    }

    const int lr0 = tid >> 1;
    const int lq0 = (tid & 1) * 2;
    const uint32_t dsm_b = smem_u32(dsm);

#pragma unroll
    for (int s = 0; s < 2; s++) {
        uint32_t sb = dsm_b + s * STG_H * 2;
#pragma unroll
        for (int mat = 0; mat < 4; mat++)
#pragma unroll
            for (int e = 0; e < 2; e++)
                cp_async16(sb + (mat * MATH + lr0 * GP + (lq0 + e) * 8) * 2,
                           srcs[mat] + (size_t)lr0 * CDIM + s * 32 + (lq0 + e) * 8);
        CP_COMMIT();
    }

    wmma::fragment<wmma::accumulator, 16, 16, 16, float> acc[4][2];
    __syncthreads();
#pragma unroll
    for (int mi = 0; mi < 4; mi++)
#pragma unroll
        for (int ni = 0; ni < 2; ni++)
            wmma::load_matrix_sync(acc[mi][ni], &sbias[wn * 32 + ni * 16], 132,
                                   wmma::mem_row_major);

    for (int kt = 0; kt < CDIM / 32; kt++) {
        CP_WAIT1();
        __syncthreads();

        const __nv_bfloat16* sm = dsm + (kt % 3) * STG_H;
#pragma unroll
        for (int ks = 0; ks < 2; ks++) {
            wmma::fragment<wmma::matrix_a, 16, 16, 16, __nv_bfloat16, wmma::row_major> fah[4], fal[4];
            wmma::fragment<wmma::matrix_b, 16, 16, 16, __nv_bfloat16, wmma::col_major> fbh[2], fbl[2];
#pragma unroll
            for (int mi = 0; mi < 4; mi++) {
                int mr = wm * 64 + mi * 16;
                wmma::load_matrix_sync(fah[mi], &sm[0 * MATH + mr * GP + ks * 16], GP);
                wmma::load_matrix_sync(fal[mi], &sm[1 * MATH + mr * GP + ks * 16], GP);
            }
#pragma unroll
            for (int ni = 0; ni < 2; ni++) {
                int nr = wn * 32 + ni * 16;
                wmma::load_matrix_sync(fbh[ni], &sm[2 * MATH + nr * GP + ks * 16], GP);
                wmma::load_matrix_sync(fbl[ni], &sm[3 * MATH + nr * GP + ks * 16], GP);
            }
#pragma unroll
            for (int mi = 0; mi < 4; mi++)
#pragma unroll
                for (int ni = 0; ni < 2; ni++) {
                    wmma::mma_sync(acc[mi][ni], fah[mi], fbh[ni], acc[mi][ni]);
                    wmma::mma_sync(acc[mi][ni], fah[mi], fbl[ni], acc[mi][ni]);
                    wmma::mma_sync(acc[mi][ni], fal[mi], fbh[ni], acc[mi][ni]);
                }
        }

        if (kt + 2 < CDIM / 32) {
            uint32_t sb = dsm_b + ((kt + 2) % 3) * STG_H * 2;
            int k0 = (kt + 2) * 32;
#pragma unroll
            for (int mat = 0; mat < 4; mat++)
#pragma unroll
                for (int e = 0; e < 2; e++)
                    cp_async16(sb + (mat * MATH + lr0 * GP + (lq0 + e) * 8) * 2,
                               srcs[mat] + (size_t)lr0 * CDIM + k0 + (lq0 + e) * 8);
        }
        CP_COMMIT();
    }

#pragma unroll
    for (int mi = 0; mi < 4; mi++)
#pragma unroll
        for (int ni = 0; ni < 2; ni++) {
            int m = m0 + wm * 64 + mi * 16;
            int n = n0 + wn * 32 + ni * 16;
            if (MODE == 0) {
                int b_ = m >> 10;
                int t0 = m & 1023;
                int h  = n >> 6;
                int d0 = n & 63;
                float* dst = &outp[(((size_t)(b_ * NH + h)) * T_SEQ + t0) * HDIM + d0];
                wmma::store_matrix_sync(dst, acc[mi][ni], HDIM, wmma::mem_row_major);
            } else {
                wmma::store_matrix_sync(&outp[(size_t)m * CDIM + n], acc[mi][ni],
                                        CDIM, wmma::mem_row_major);
            }
        }
}

// ---------------------------------------------------------------------------
// Flash attention on mma.sync; K/V fragments via ldmatrix.x4
// (one LDSM loads bh0,bh1,bl0,bl1 together). 256 threads, 128-row q tiles,
// double-buffered K/V.
// ---------------------------------------------------------------------------
#define KP 72
#define BUF_H 18432
#define FA_SMEM (2 * BUF_H * 2 + 4096)

__global__ __launch_bounds__(256, 1)
void fa_kernel(const float* __restrict__ attn_bias)
{
    extern __shared__ char fsh[];
    __nv_bfloat16* sA    = (__nv_bfloat16*)fsh;
    float*         sbias = (float*)(fsh + 2 * BUF_H * 2);

    const int bh = blockIdx.y;
    const int h  = bh & (NH - 1);
    const int b_ = bh >> 3;
    const int qt = (int)(gridDim.x - 1) - (int)blockIdx.x;
    const int tid = threadIdx.x;
    const int w   = tid >> 5, lane = tid & 31;
    const int gid = lane >> 2, tig = lane & 3;

    const float* qg = g_q + (size_t)bh * T_SEQ * HDIM + (size_t)qt * 128 * HDIM;
    const __nv_bfloat16* khg = g_khi + (size_t)bh * T_SEQ * HDIM;
    const __nv_bfloat16* klg = g_klo + (size_t)bh * T_SEQ * HDIM;
    const __nv_bfloat16* vhg = g_vhi + (size_t)bh * HDIM * T_SEQ;
    const __nv_bfloat16* vlg = g_vlo + (size_t)bh * HDIM * T_SEQ;

    for (int i = tid; i < 128 * 16; i += 256) {
        int row = i >> 4, c4 = (i & 15) * 4;
        float4 v = *(const float4*)&qg[(size_t)row * HDIM + c4];
        float f[4] = {v.x, v.y, v.z, v.w};
        __nv_bfloat16 hh[4], ll[4];
        split4(f, hh, ll);
#pragma unroll
        for (int j = 0; j < 4; j++) {
            sA[row * KP + c4 + j]        = hh[j];
            sA[9216 + row * KP + c4 + j] = ll[j];
        }
    }
    if (qt < 4) {
        const float* bsrc = attn_bias + h * 64 * 64 + (qt * 16) * 64;
        for (int i = tid; i < 16 * 64; i += 256) sbias[i] = bsrc[i];
    }
    __syncthreads();

    uint32_t qh[4][4], ql[4][4];
    const int qrl = w * 16 + gid;
#pragma unroll
    for (int ks = 0; ks < 4; ks++) {
        int ad = qrl * KP + ks * 16 + 2 * tig;
        qh[ks][0] = *(const uint32_t*)&sA[ad];
        qh[ks][1] = *(const uint32_t*)&sA[ad + 8 * KP];
        qh[ks][2] = *(const uint32_t*)&sA[ad + 8];
        qh[ks][3] = *(const uint32_t*)&sA[ad + 8 * KP + 8];
        ql[ks][0] = *(const uint32_t*)&sA[9216 + ad];
        ql[ks][1] = *(const uint32_t*)&sA[9216 + ad + 8 * KP];
        ql[ks][2] = *(const uint32_t*)&sA[9216 + ad + 8];
        ql[ks][3] = *(const uint32_t*)&sA[9216 + ad + 8 * KP + 8];
    }
    __syncthreads();

    const int ktmax = 2 * qt + 1;
    const int crow = tid >> 1;
    const int cseg = (tid & 1) * 4;

    // ldmatrix lane offset (bytes): 4 matrices = (hi,k0-7),(hi,k8-15),(lo,k0-7),(lo,k8-15)
    const int grp = lane >> 3, r8 = lane & 7;
    const uint32_t lmo = (uint32_t)((((grp >> 1) * 4608) + r8 * KP + (grp & 1) * 8) * 2);
    const uint32_t sA_a = smem_u32(sA);

    {
        const int kt = 0;
        __nv_bfloat16* dst = sA;
        const __nv_bfloat16* shi = (crow < 64) ? khg : (vhg - 64 * T_SEQ);
        const __nv_bfloat16* slo = (crow < 64) ? klg : (vlg - 64 * T_SEQ);
        int row = crow & 63;
        size_t soff = (crow < 64) ? ((size_t)(kt * 64 + row) * HDIM)
                                  : ((size_t)(crow) * T_SEQ + kt * 64);
        int doff = ((crow < 64) ? 0 : 9216) + row * KP;
#pragma unroll
        for (int e = 0; e < 4; e++) {
            *(uint4*)&dst[doff + (cseg + e) * 8] =
                *(const uint4*)&shi[soff + (cseg + e) * 8];
            *(uint4*)&dst[4608 + doff + (cseg + e) * 8] =
                *(const uint4*)&slo[soff + (cseg + e) * 8];
        }
    }
    __syncthreads();

    float m0 = -1e30f, m1 = -1e30f, l0 = 0.f, l1 = 0.f;
    float oacc[8][4] = {};
    const int qr0 = qt * 128 + w * 16 + gid;
    const int qr1 = qr0 + 8;

    for (int kt = 0; kt <= ktmax; kt++) {
        if (kt < ktmax) {
            const int nk = kt + 1;
            __nv_bfloat16* dst = sA + ((nk & 1) ? BUF_H : 0);
            const __nv_bfloat16* shi = (crow < 64) ? khg : (vhg - 64 * T_SEQ);
            const __nv_bfloat16* slo = (crow < 64) ? klg : (vlg - 64 * T_SEQ);
            int row = crow & 63;
            size_t soff = (crow < 64) ? ((size_t)(nk * 64 + row) * HDIM)
                                      : ((size_t)(crow) * T_SEQ + nk * 64);
            int doff = ((crow < 64) ? 0 : 9216) + row * KP;
#pragma unroll
            for (int e = 0; e < 4; e++) {
                *(uint4*)&dst[doff + (cseg + e) * 8] =
                    *(const uint4*)&shi[soff + (cseg + e) * 8];
                *(uint4*)&dst[4608 + doff + (cseg + e) * 8] =
                    *(const uint4*)&slo[soff + (cseg + e) * 8];
            }
        }

        if (kt * 64 <= qt * 128 + w * 16 + 15) {
            const uint32_t kbase = sA_a + ((kt & 1) ? BUF_H * 2 : 0) + lmo;
            const uint32_t vbase = kbase + 9216 * 2;

            // ---- S = Q K^T (ldmatrix.x4: one op -> bh0,bh1,bl0,bl1) ----
            float sacc[8][4] = {};
#pragma unroll
            for (int nt = 0; nt < 8; nt++)
#pragma unroll
                for (int ks = 0; ks < 4; ks++) {
                    uint32_t kb[4];
                    ldsm_x4(kb, kbase + (uint32_t)((nt * 8 * KP + ks * 16) * 2));
                    mma_bf16(sacc[nt], qh[ks], kb[0], kb[1]);
                    mma_bf16(sacc[nt], qh[ks], kb[2], kb[3]);
                    mma_bf16(sacc[nt], ql[ks], kb[0], kb[1]);
                }

            // ---- scale + bias + masks ----
#pragma unroll
            for (int nt = 0; nt < 8; nt++) {
                float bb0 = 0.f, bb1 = 0.f;
                if (qt < 4) {
                    bb0 = sbias[(2 * w) * 64 + kt * 8 + nt];
                    bb1 = sbias[(2 * w + 1) * 64 + kt * 8 + nt];
                }
#pragma unroll
                for (int c = 0; c < 4; c++) {
                    int kcol = kt * 64 + nt * 8 + 2 * tig + (c & 1);
                    int qr   = (c < 2) ? qr0 : qr1;
                    float s  = sacc[nt][c] * SCALE_F + ((c < 2) ? bb0 : bb1);
                    if (kcol > qr || (kcol & 15) == 15) s = -1e30f;
                    sacc[nt][c] = s;
                }
            }

            // ---- online softmax ----
            float rm0 = -1e30f, rm1 = -1e30f;
#pragma unroll
            for (int nt = 0; nt < 8; nt++) {
                rm0 = fmaxf(rm0, fmaxf(sacc[nt][0], sacc[nt][1]));
                rm1 = fmaxf(rm1, fmaxf(sacc[nt][2], sacc[nt][3]));
            }
            rm0 = fmaxf(rm0, __shfl_xor_sync(0xffffffffu, rm0, 1));
            rm0 = fmaxf(rm0, __shfl_xor_sync(0xffffffffu, rm0, 2));
            rm1 = fmaxf(rm1, __shfl_xor_sync(0xffffffffu, rm1, 1));
            rm1 = fmaxf(rm1, __shfl_xor_sync(0xffffffffu, rm1, 2));
            float mn0 = fmaxf(m0, rm0), mn1 = fmaxf(m1, rm1);
            float a0 = __expf(m0 - mn0), a1 = __expf(m1 - mn1);
            float rs0 = 0.f, rs1 = 0.f;
#pragma unroll
            for (int nt = 0; nt < 8; nt++) {
                sacc[nt][0] = __expf(sacc[nt][0] - mn0);
                sacc[nt][1] = __expf(sacc[nt][1] - mn0);
                sacc[nt][2] = __expf(sacc[nt][2] - mn1);
                sacc[nt][3] = __expf(sacc[nt][3] - mn1);
                rs0 += sacc[nt][0] + sacc[nt][1];
                rs1 += sacc[nt][2] + sacc[nt][3];
            }
            rs0 += __shfl_xor_sync(0xffffffffu, rs0, 1);
            rs0 += __shfl_xor_sync(0xffffffffu, rs0, 2);
            rs1 += __shfl_xor_sync(0xffffffffu, rs1, 1);
            rs1 += __shfl_xor_sync(0xffffffffu, rs1, 2);
            l0 = l0 * a0 + rs0; m0 = mn0;
            l1 = l1 * a1 + rs1; m1 = mn1;
#pragma unroll
            for (int dt = 0; dt < 8; dt++) {
                oacc[dt][0] *= a0; oacc[dt][1] *= a0;
                oacc[dt][2] *= a1; oacc[dt][3] *= a1;
            }

            // ---- P -> A-fragments from S accumulators (hi/lo) ----
            uint32_t ph[4][4], pl[4][4];
#pragma unroll
            for (int ks = 0; ks < 4; ks++)
#pragma unroll
                for (int half = 0; half < 2; half++) {
                    int nt = 2 * ks + half;
#pragma unroll
                    for (int rr = 0; rr < 2; rr++) {
                        float pe = sacc[nt][rr * 2 + 0];
                        float po = sacc[nt][rr * 2 + 1];
                        float he = __bfloat162float(__float2bfloat16(pe));
                        float ho = __bfloat162float(__float2bfloat16(po));
                        ph[ks][half * 2 + rr] = pack_bf2(he, ho);
                        pl[ks][half * 2 + rr] = pack_bf2(pe - he, po - ho);
                    }
                }

            // ---- O += P V (ldmatrix.x4) ----
#pragma unroll
            for (int dt = 0; dt < 8; dt++)
#pragma unroll
                for (int ks = 0; ks < 4; ks++) {
                    uint32_t vb[4];
                    ldsm_x4(vb, vbase + (uint32_t)((dt * 8 * KP + ks * 16) * 2));
                    mma_bf16(oacc[dt], ph[ks], vb[0], vb[1]);
                    mma_bf16(oacc[dt], ph[ks], vb[2], vb[3]);
                    mma_bf16(oacc[dt], pl[ks], vb[0], vb[1]);
                }
        }
        __syncthreads();
    }

    float inv0 = 1.0f / l0, inv1 = 1.0f / l1;
#pragma unroll
    for (int dt = 0; dt < 8; dt++) {
        int dcol = h * 64 + dt * 8 + 2 * tig;
        float y00 = oacc[dt][0] * inv0, y01 = oacc[dt][1] * inv0;
        float y10 = oacc[dt][2] * inv1, y11 = oacc[dt][3] * inv1;
        float h00 = __bfloat162float(__float2bfloat16(y00));
        float h01 = __bfloat162float(__float2bfloat16(y01));
        float h10 = __bfloat162float(__float2bfloat16(y10));
        float h11 = __bfloat162float(__float2bfloat16(y11));
        size_t i0 = ((size_t)(b_ * T_SEQ + qr0)) * CDIM + dcol;
        size_t i1 = ((size_t)(b_ * T_SEQ + qr1)) * CDIM + dcol;
        *(uint32_t*)&g_yhi[i0] = pack_bf2(h00, h01);
        *(uint32_t*)&g_ylo[i0] = pack_bf2(y00 - h00, y01 - h01);
        *(uint32_t*)&g_yhi[i1] = pack_bf2(h10, h11);
        *(uint32_t*)&g_ylo[i1] = pack_bf2(y10 - h10, y11 - h11);
    }
}

// ---------------------------------------------------------------------------

extern "C" void kernel_launch(void* const* d_in, const int* in_sizes, int n_in,
                              void* d_out, int out_size)
{
    const float* x  = (const float*)d_in[0];
    const float* ab = (const float*)d_in[1];
    const float* Wq = (const float*)d_in[2];
    const float* bq = (const float*)d_in[3];
    const float* Wk = (const float*)d_in[4];
    const float* bk = (const float*)d_in[5];
    const float* Wv = (const float*)d_in[6];
    const float* bv = (const float*)d_in[7];
    const float* Wp = (const float*)d_in[8];
    const float* bp = (const float*)d_in[9];
    float* out = (float*)d_out;

    // bf16 hi/lo conversions
    convert_x<<<(BATCH * T_SEQ * CDIM) / 1024, 256>>>(x);
    convert_w4<<<dim3((CDIM * CDIM) / 1024, 4), 256>>>(Wq, Wk, Wv, Wp);

    // QKV projections (wmma + cp.async pipeline)
    cudaFuncSetAttribute(hm_gemm<0>, cudaFuncAttributeMaxDynamicSharedMemorySize,
                         GEMM_SMEM);
    hm_gemm<0><<<dim3(CDIM / 128, (BATCH * T_SEQ) / 128, 3), 256, GEMM_SMEM>>>(
        bq, bk, bv, nullptr);

    // Pre-convert K/V to MMA-ready bf16 (V transposed)
    convert_kv<<<dim3(T_SEQ / 64, BATCH * NH), 256>>>();

    // Flash attention (mma.sync + ldmatrix)
    cudaFuncSetAttribute(fa_kernel, cudaFuncAttributeMaxDynamicSharedMemorySize,
                         FA_SMEM);
    fa_kernel<<<dim3(T_SEQ / 128, BATCH * NH), 256, FA_SMEM>>>(ab);

    // Output projection
    cudaFuncSetAttribute(hm_gemm<1>, cudaFuncAttributeMaxDynamicSharedMemorySize,
                         GEMM_SMEM);
    hm_gemm<1><<<dim3(CDIM / 128, (BATCH * T_SEQ) / 128, 1), 256, GEMM_SMEM>>>(
        bp, nullptr, nullptr, out);
}